// round 6
// baseline (speedup 1.0000x reference)
#include <cuda_runtime.h>
#include <cuda_fp16.h>
#include <math.h>

#define N_IN   128
#define NLAY   6
#define N_H    320
#define DEG    32
#define N_OUT  18
#define BATCH  8192
#define BT     64            // batch rows per CTA (2 per lane via half2)
#define PAIRS  32            // row-pairs per tile == lanes
#define SMEM_NODES 1728      // N_IN + 5*N_H kept in shared
#define NTILES (BATCH / BT)  // 128 CTAs, single wave
#define NWARPS 20
#define NTHREADS (NWARPS * 32)       // 640 -> ~102 regs/thread available
#define GSZ    40                    // neurons per group (2 per warp), layer-aligned
#define NGROUPS (NLAY * N_H / GSZ)   // 48
#define LASTL_M (5 * (N_H / GSZ))    // m >= 40 -> layer 5 (scratch store)
#define SWORDS (GSZ * DEG)           // 1280 stage words (2 per thread)
#define HWORDS (N_OUT * DEG)         // 576 head stage words

// Layer-5 activations (nodes [1728,2048)); head re-gathers them from global.
__device__ __half2 g_scratch[(size_t)NTILES * N_H * PAIRS];

struct SMem {
    __half2 acts[SMEM_NODES * PAIRS];  // 221,184 B node-major, pair = lane
    int     sidx[SWORDS];              //   5,120 B idx stage
    __half2 sw  [SWORDS];              //   5,120 B weight stage, packed (w,w)
};                                      // 231,424 B total (cap 232,448)

__global__ void __launch_bounds__(NTHREADS, 1)
policy_kernel(const float* __restrict__ obs,      // [BATCH, N_IN]
              const int*   __restrict__ hid_src,  // [NLAY*N_H*DEG] flat
              const float* __restrict__ hid_w,    // [NLAY*N_H*DEG] flat
              const float* __restrict__ hid_b,    // [NLAY*N_H] flat
              const int*   __restrict__ out_src,  // [N_OUT, DEG]
              const float* __restrict__ out_w,    // [N_OUT, DEG]
              const float* __restrict__ out_b,    // [N_OUT]
              float*       __restrict__ out)      // [BATCH, N_OUT]
{
    extern __shared__ char raw[];
    SMem* s = (SMem*)raw;
    const int tid  = threadIdx.x;
    const int lane = tid & 31;
    const int warp = tid >> 5;
    const int tile = blockIdx.x;

    // ---- obs -> node-major half2 smem. Lane p owns batch rows (2p, 2p+1).
    {
        const int r0 = tile * BT + 2 * lane;
        const float4* o0 = (const float4*)(obs + (size_t)r0 * N_IN);
        const float4* o1 = (const float4*)(obs + (size_t)(r0 + 1) * N_IN);
        for (int q = warp; q < N_IN / 4; q += NWARPS) {
            float4 a = o0[q], b = o1[q];
            s->acts[(q * 4 + 0) * PAIRS + lane] = __floats2half2_rn(a.x, b.x);
            s->acts[(q * 4 + 1) * PAIRS + lane] = __floats2half2_rn(a.y, b.y);
            s->acts[(q * 4 + 2) * PAIRS + lane] = __floats2half2_rn(a.z, b.z);
            s->acts[(q * 4 + 3) * PAIRS + lane] = __floats2half2_rn(a.w, b.w);
        }
    }

    __half2* __restrict__ sa  = s->acts + lane;
    __half2* __restrict__ scr = g_scratch + (size_t)tile * (N_H * PAIRS) + lane;

    // ---- Preload group m=0 (2 words per thread).
    s->sidx[tid]            = hid_src[tid];
    s->sw  [tid]            = __float2half2_rn(hid_w[tid]);
    s->sidx[tid + NTHREADS] = hid_src[tid + NTHREADS];
    s->sw  [tid + NTHREADS] = __float2half2_rn(hid_w[tid + NTHREADS]);
    __syncthreads();

    int off = SWORDS;                 // flat word offset of group m+1
    int p0i = 0, p1i = 0;
    __half2 p0w = __floats2half2_rn(0.f, 0.f), p1w = p0w;

    for (int m = 0; m < NGROUPS; m++) {
        // ---- prefetch next stage words into registers (overlaps compute)
        if (m + 1 < NGROUPS) {
            p0i = hid_src[off + tid];
            p0w = __float2half2_rn(hid_w[off + tid]);
            p1i = hid_src[off + tid + NTHREADS];
            p1w = __float2half2_rn(hid_w[off + tid + NTHREADS]);
        } else if (tid < HWORDS) {    // head stage (single word per thread)
            p0i = out_src[tid];
            p0w = __float2half2_rn(out_w[tid]);
        }
        off += SWORDS;

        // ---- compute: warp = neurons (n0 = base+warp, n1 = base+20+warp)
        const int4*  ip0 = (const int4*) (s->sidx + warp * DEG);
        const uint4* wp0 = (const uint4*)(s->sw   + warp * DEG);
        const int4*  ip1 = (const int4*) (s->sidx + (warp + NWARPS) * DEG);
        const uint4* wp1 = (const uint4*)(s->sw   + (warp + NWARPS) * DEG);
        __half2 a0[8], a1[8];
        #pragma unroll
        for (int k = 0; k < 8; k++) { a0[k] = __floats2half2_rn(0.f, 0.f); a1[k] = a0[k]; }
        #pragma unroll
        for (int c = 0; c < DEG / 4; c++) {
            const int4  i4 = ip0[c];  const uint4 w4 = wp0[c];
            const int4  j4 = ip1[c];  const uint4 x4 = wp1[c];
            const int k = (c & 1) * 4;    // 8 chains x 4 terms per neuron
            a0[k + 0] = __hfma2(sa[i4.x * PAIRS], *(const __half2*)&w4.x, a0[k + 0]);
            a1[k + 0] = __hfma2(sa[j4.x * PAIRS], *(const __half2*)&x4.x, a1[k + 0]);
            a0[k + 1] = __hfma2(sa[i4.y * PAIRS], *(const __half2*)&w4.y, a0[k + 1]);
            a1[k + 1] = __hfma2(sa[j4.y * PAIRS], *(const __half2*)&x4.y, a1[k + 1]);
            a0[k + 2] = __hfma2(sa[i4.z * PAIRS], *(const __half2*)&w4.z, a0[k + 2]);
            a1[k + 2] = __hfma2(sa[j4.z * PAIRS], *(const __half2*)&x4.z, a1[k + 2]);
            a0[k + 3] = __hfma2(sa[i4.w * PAIRS], *(const __half2*)&w4.w, a0[k + 3]);
            a1[k + 3] = __hfma2(sa[j4.w * PAIRS], *(const __half2*)&x4.w, a1[k + 3]);
        }
        // fp32 epilogue (sequential convert-accumulate, identical to R5 numerics)
        const float b0 = hid_b[m * GSZ + warp];
        const float b1 = hid_b[m * GSZ + NWARPS + warp];
        float s0l = b0, s0h = b0, s1l = b1, s1h = b1;
        #pragma unroll
        for (int k = 0; k < 8; k++) {
            const float2 f = __half22float2(a0[k]); s0l += f.x; s0h += f.y;
            const float2 g = __half22float2(a1[k]); s1l += g.x; s1h += g.y;
        }
        const __half2 h0 = __floats2half2_rn(tanhf(s0l), tanhf(s0h));
        const __half2 h1 = __floats2half2_rn(tanhf(s1l), tanhf(s1h));
        const int node0 = N_IN + m * GSZ + warp;          // node1 = node0 + 20
        if (m < LASTL_M) {
            sa[node0 * PAIRS] = h0;
            sa[(node0 + NWARPS) * PAIRS] = h1;
        } else {
            scr[(node0 - SMEM_NODES) * PAIRS] = h0;
            scr[(node0 + NWARPS - SMEM_NODES) * PAIRS] = h1;
        }

        __syncthreads();              // all stage reads done
        if (m + 1 < NGROUPS) {
            s->sidx[tid] = p0i;             s->sw[tid] = p0w;
            s->sidx[tid + NTHREADS] = p1i;  s->sw[tid + NTHREADS] = p1w;
        } else if (tid < HWORDS) {
            s->sidx[tid] = p0i;             s->sw[tid] = p0w;
        }
        __syncthreads();              // stage + this group's acts ready
    }

    // ---- output head: 18 neurons (warps 0..17); sources may hit scratch.
    if (warp < N_OUT) {
        const int4*  ip = (const int4*) (s->sidx + warp * DEG);
        const uint4* wp = (const uint4*)(s->sw   + warp * DEG);
        __half2 acc[8];
        #pragma unroll
        for (int k = 0; k < 8; k++) acc[k] = __floats2half2_rn(0.f, 0.f);
        #pragma unroll
        for (int c = 0; c < DEG / 4; c++) {
            const int4  i4 = ip[c];
            const uint4 w4 = wp[c];
            const int k = (c & 1) * 4;
            #define GATH(II, WW, KK) { const int ii = (II);                           \
                const __half2 v = (ii < SMEM_NODES) ? sa[ii * PAIRS]                  \
                                                    : scr[(ii - SMEM_NODES) * PAIRS]; \
                acc[KK] = __hfma2(v, *(const __half2*)&(WW), acc[KK]); }
            GATH(i4.x, w4.x, k + 0); GATH(i4.y, w4.y, k + 1);
            GATH(i4.z, w4.z, k + 2); GATH(i4.w, w4.w, k + 3);
            #undef GATH
        }
        const float bo = out_b[warp];
        float sl = bo, sh = bo;
        #pragma unroll
        for (int k = 0; k < 8; k++) {
            const float2 f = __half22float2(acc[k]);
            sl += f.x; sh += f.y;
        }
        const int r0 = tile * BT + 2 * lane;
        out[(size_t)r0       * N_OUT + warp] = tanhf(sl);
        out[(size_t)(r0 + 1) * N_OUT + warp] = tanhf(sh);
    }
}

extern "C" void kernel_launch(void* const* d_in, const int* in_sizes, int n_in,
                              void* d_out, int out_size)
{
    const float* obs     = (const float*)d_in[0];
    const int*   hid_src = (const int*)  d_in[1];
    const float* hid_w   = (const float*)d_in[2];
    const float* hid_b   = (const float*)d_in[3];
    const int*   out_src = (const int*)  d_in[4];
    const float* out_w   = (const float*)d_in[5];
    const float* out_b   = (const float*)d_in[6];
    float*       out     = (float*)d_out;

    const size_t smem = sizeof(SMem);  // 231,424 B
    cudaFuncSetAttribute(policy_kernel,
                         cudaFuncAttributeMaxDynamicSharedMemorySize, (int)smem);
    policy_kernel<<<NTILES, NTHREADS, smem>>>(obs, hid_src, hid_w, hid_b,
                                              out_src, out_w, out_b, out);
}

// round 7
// speedup vs baseline: 1.7499x; 1.7499x over previous
#include <cuda_runtime.h>
#include <cuda_fp16.h>
#include <math.h>

#define N_IN   128
#define NLAY   6
#define N_H    320
#define DEG    32
#define N_OUT  18
#define BATCH  8192
#define BT     64              // batch rows per CTA (2 per lane via half2)
#define PAIRS  32              // row-pairs per tile == lanes
#define SMEM_NODES 1680        // nodes resident in shared (rest -> scratch)
#define SCR_NODES  (2048 - SMEM_NODES)   // 368
#define NTILES (BATCH / BT)    // 128 CTAs, single wave
#define NWARPS 32
#define NTHREADS (NWARPS * 32) // 1024
#define GSZ    32              // neurons per group (== NWARPS)
#define NGROUPS (NLAY * N_H / GSZ)   // 60
#define FASTG  50              // groups 0..49 (layers 0-4): sources < 1408 -> pure smem
#define SWORDS (GSZ * DEG)     // 1024 stage words (1 per thread)
#define HWORDS (N_OUT * DEG)   // 576 head stage words

// Spilled activations (nodes [1680,2048)); guarded gathers read them back.
__device__ __half2 g_scratch[(size_t)NTILES * SCR_NODES * PAIRS];

struct SMem {
    __half2 acts[SMEM_NODES * PAIRS];  // 215,040 B node-major, pair = lane
    int     sidx[2][SWORDS];           //   8,192 B double-buffered idx stage
    __half2 sw  [2][SWORDS];           //   8,192 B double-buffered (w,w) stage
};                                      // 231,424 B total (cap 232,448)

__device__ __forceinline__ float fast_tanh(float x) {
    float y;
    asm("tanh.approx.f32 %0, %1;" : "=f"(y) : "f"(x));
    return y;
}

// One group's neuron compute: warp = one neuron x 64 batch rows.
// GUARD=true adds the scratch fallback for indices >= SMEM_NODES (layer 5 only).
template<bool GUARD>
__device__ __forceinline__ void group_compute(
    const int* __restrict__ sidx, const __half2* __restrict__ sw,
    const __half2* __restrict__ sa, const __half2* __restrict__ scr,
    __half2* __restrict__ sa_mut, __half2* __restrict__ scr_mut,
    const float* __restrict__ hid_b, int m, int warp)
{
    const int4*  ip = (const int4*) (sidx + warp * DEG);  // LDS.128 bcast
    const uint4* wp = (const uint4*)(sw   + warp * DEG);  // LDS.128 bcast
    __half2 acc[8];
    #pragma unroll
    for (int k = 0; k < 8; k++) acc[k] = __floats2half2_rn(0.f, 0.f);
    #pragma unroll
    for (int c = 0; c < DEG / 4; c++) {
        const int4  i4 = ip[c];
        const uint4 w4 = wp[c];
        const int k = (c & 1) * 4;     // 8 chains x 4 terms (R5 numerics)
        #define GLOAD(II) (GUARD ? (((II) < SMEM_NODES) ? sa[(II) * PAIRS]             \
                                     : scr[((II) - SMEM_NODES) * PAIRS])               \
                                 : sa[(II) * PAIRS])
        acc[k + 0] = __hfma2(GLOAD(i4.x), *(const __half2*)&w4.x, acc[k + 0]);
        acc[k + 1] = __hfma2(GLOAD(i4.y), *(const __half2*)&w4.y, acc[k + 1]);
        acc[k + 2] = __hfma2(GLOAD(i4.z), *(const __half2*)&w4.z, acc[k + 2]);
        acc[k + 3] = __hfma2(GLOAD(i4.w), *(const __half2*)&w4.w, acc[k + 3]);
        #undef GLOAD
    }
    const float bb = hid_b[m * GSZ + warp];
    float sl = bb, sh = bb;
    #pragma unroll
    for (int k = 0; k < 8; k++) {
        const float2 f = __half22float2(acc[k]);
        sl += f.x; sh += f.y;
    }
    const __half2 hv = __floats2half2_rn(fast_tanh(sl), fast_tanh(sh));
    const int node = N_IN + m * GSZ + warp;
    if (node < SMEM_NODES) sa_mut [node * PAIRS] = hv;                 // STS
    else                   scr_mut[(node - SMEM_NODES) * PAIRS] = hv;  // STG
}

__global__ void __launch_bounds__(NTHREADS, 1)
policy_kernel(const float* __restrict__ obs,      // [BATCH, N_IN]
              const int*   __restrict__ hid_src,  // [NLAY*N_H*DEG] flat
              const float* __restrict__ hid_w,    // [NLAY*N_H*DEG] flat
              const float* __restrict__ hid_b,    // [NLAY*N_H] flat
              const int*   __restrict__ out_src,  // [N_OUT, DEG]
              const float* __restrict__ out_w,    // [N_OUT, DEG]
              const float* __restrict__ out_b,    // [N_OUT]
              float*       __restrict__ out)      // [BATCH, N_OUT]
{
    extern __shared__ char raw[];
    SMem* s = (SMem*)raw;
    const int tid  = threadIdx.x;
    const int lane = tid & 31;
    const int warp = tid >> 5;
    const int tile = blockIdx.x;

    // ---- obs -> node-major half2 smem. Lane p owns batch rows (2p, 2p+1).
    {
        const int r0 = tile * BT + 2 * lane;
        const float4* o0 = (const float4*)(obs + (size_t)r0 * N_IN);
        const float4* o1 = (const float4*)(obs + (size_t)(r0 + 1) * N_IN);
        const int q = warp;                // 32 warps cover N_IN/4 = 32 quads
        float4 a = o0[q], b = o1[q];
        s->acts[(q * 4 + 0) * PAIRS + lane] = __floats2half2_rn(a.x, b.x);
        s->acts[(q * 4 + 1) * PAIRS + lane] = __floats2half2_rn(a.y, b.y);
        s->acts[(q * 4 + 2) * PAIRS + lane] = __floats2half2_rn(a.z, b.z);
        s->acts[(q * 4 + 3) * PAIRS + lane] = __floats2half2_rn(a.w, b.w);
    }

    const __half2* __restrict__ sa = s->acts + lane;
    __half2* __restrict__ sa_mut   = s->acts + lane;
    __half2* __restrict__ scr_mut  = g_scratch + (size_t)tile * (SCR_NODES * PAIRS) + lane;
    const __half2* __restrict__ scr = scr_mut;

    // ---- Preload stage for group m=0 into buffer 0.
    s->sidx[0][tid] = hid_src[tid];
    s->sw  [0][tid] = __float2half2_rn(hid_w[tid]);
    __syncthreads();

    int buf = 0;
    // ---- Fast groups (layers 0-4): pure-smem gathers.
    for (int m = 0; m < FASTG; m++) {
        // prefetch next stage (LDG at top: latency hidden under compute)
        const int pidx = hid_src[(m + 1) * SWORDS + tid];
        const float pw = hid_w [(m + 1) * SWORDS + tid];

        group_compute<false>(s->sidx[buf], s->sw[buf], sa, scr, sa_mut, scr_mut,
                             hid_b, m, warp);

        s->sidx[buf ^ 1][tid] = pidx;           // STS after compute
        s->sw  [buf ^ 1][tid] = __float2half2_rn(pw);
        __syncthreads();                        // single barrier per group
        buf ^= 1;
    }
    // ---- Guarded groups (layer 5): gathers may hit scratch.
    for (int m = FASTG; m < NGROUPS; m++) {
        int pidx = 0; float pw = 0.f;
        const bool have = (m + 1 < NGROUPS) || (tid < HWORDS);
        if (m + 1 < NGROUPS)   { pidx = hid_src[(m + 1) * SWORDS + tid];
                                 pw   = hid_w [(m + 1) * SWORDS + tid]; }
        else if (tid < HWORDS) { pidx = out_src[tid]; pw = out_w[tid]; }

        group_compute<true>(s->sidx[buf], s->sw[buf], sa, scr, sa_mut, scr_mut,
                            hid_b, m, warp);

        if (have) {
            s->sidx[buf ^ 1][tid] = pidx;
            s->sw  [buf ^ 1][tid] = __float2half2_rn(pw);
        }
        __syncthreads();
        buf ^= 1;
    }

    // ---- output head: 18 neurons (warps 0..17); accurate tanh on outputs.
    if (warp < N_OUT) {
        const int4*  ip = (const int4*) (s->sidx[buf] + warp * DEG);
        const uint4* wp = (const uint4*)(s->sw  [buf] + warp * DEG);
        __half2 acc[8];
        #pragma unroll
        for (int k = 0; k < 8; k++) acc[k] = __floats2half2_rn(0.f, 0.f);
        #pragma unroll
        for (int c = 0; c < DEG / 4; c++) {
            const int4  i4 = ip[c];
            const uint4 w4 = wp[c];
            const int k = (c & 1) * 4;
            #define GATH(II, WW, KK) { const int ii = (II);                           \
                const __half2 v = (ii < SMEM_NODES) ? sa[ii * PAIRS]                  \
                                                    : scr[(ii - SMEM_NODES) * PAIRS]; \
                acc[KK] = __hfma2(v, *(const __half2*)&(WW), acc[KK]); }
            GATH(i4.x, w4.x, k + 0); GATH(i4.y, w4.y, k + 1);
            GATH(i4.z, w4.z, k + 2); GATH(i4.w, w4.w, k + 3);
            #undef GATH
        }
        const float bo = out_b[warp];
        float sl = bo, sh = bo;
        #pragma unroll
        for (int k = 0; k < 8; k++) {
            const float2 f = __half22float2(acc[k]);
            sl += f.x; sh += f.y;
        }
        const int r0 = tile * BT + 2 * lane;
        out[(size_t)r0       * N_OUT + warp] = tanhf(sl);
        out[(size_t)(r0 + 1) * N_OUT + warp] = tanhf(sh);
    }
}

extern "C" void kernel_launch(void* const* d_in, const int* in_sizes, int n_in,
                              void* d_out, int out_size)
{
    const float* obs     = (const float*)d_in[0];
    const int*   hid_src = (const int*)  d_in[1];
    const float* hid_w   = (const float*)d_in[2];
    const float* hid_b   = (const float*)d_in[3];
    const int*   out_src = (const int*)  d_in[4];
    const float* out_w   = (const float*)d_in[5];
    const float* out_b   = (const float*)d_in[6];
    float*       out     = (float*)d_out;

    const size_t smem = sizeof(SMem);  // 231,424 B
    cudaFuncSetAttribute(policy_kernel,
                         cudaFuncAttributeMaxDynamicSharedMemorySize, (int)smem);
    policy_kernel<<<NTILES, NTHREADS, smem>>>(obs, hid_src, hid_w, hid_b,
                                              out_src, out_w, out_b, out);
}